// round 15
// baseline (speedup 1.0000x reference)
#include <cuda_runtime.h>
#include <cuda_bf16.h>
#include <cstdint>

// Problem constants (fixed by the reference)
#define N_SAMPLES 4096
#define D_IN      1024
#define B_MID     512
#define E_TASKS   16
#define L1_LAMBDA 1e-4f
#define L1_SLICES 32   // W1 slices per expert (512 W-blocks in prep)

// GEMM tiling: block 64(M) x 128(N) x 64(K), 8 warps (2m x 4n), 2-stage
#define BM 64
#define BN 128
#define BK 64
#define NTHREADS 256
#define NITER (D_IN / BK)   // 16
#define MAXJOBS 80          // sum_e ceil(cnt_e/BM) <= 4096/64 + 16

// Dynamic smem (bytes). Stage = {Ah 8K, Al 8K, Bh 16K, Bl 16K} = 48K.
// Rows are 128B wide (64 bf16), SW128 swizzle chunk' = c ^ (row&7).
#define ST_AL 8192
#define ST_BH 16384
#define ST_BL 32768
#define STAGE_B 49152
#define OFF_ROWS  (2 * STAGE_B)            // 64 ints
#define OFF_PART  (OFF_ROWS + 256)         // 64 x 4 floats
#define SMEM_BYTES (OFF_PART + 1024)       // 99584

// Static device scratch (no allocations allowed; zero-initialized at load)
__device__ __nv_bfloat16 g_xhi[(size_t)N_SAMPLES * D_IN];
__device__ __nv_bfloat16 g_xlo[(size_t)N_SAMPLES * D_IN];
__device__ __nv_bfloat16 g_whi[(size_t)E_TASKS * B_MID * D_IN];
__device__ __nv_bfloat16 g_wlo[(size_t)E_TASKS * B_MID * D_IN];
__device__ float g_part[(size_t)N_SAMPLES * 4];   // layer-2 partials per n-block
__device__ int   g_perm[N_SAMPLES];
__device__ int   g_counts[E_TASKS];
__device__ int   g_offsets[E_TASKS];
__device__ int   g_jobs[MAXJOBS];                 // packed (e<<16)|mtile
__device__ int   g_njobs;
__device__ float g_l1part[E_TASKS * L1_SLICES];
__device__ float g_l1small[E_TASKS];

// ---------------------------------------------------------------------------
// Split helpers: pack two floats -> bf16x2 hi word + bf16x2 lo-residual word.
// ---------------------------------------------------------------------------
__device__ __forceinline__ void split2(float a, float b,
                                       uint32_t& hp, uint32_t& lp)
{
    __nv_bfloat16 ha = __float2bfloat16_rn(a);
    __nv_bfloat16 hb = __float2bfloat16_rn(b);
    __nv_bfloat162 hh(ha, hb);
    hp = *reinterpret_cast<uint32_t*>(&hh);
    __nv_bfloat162 ll(__float2bfloat16_rn(a - __bfloat162float(ha)),
                      __float2bfloat16_rn(b - __bfloat162float(hb)));
    lp = *reinterpret_cast<uint32_t*>(&ll);
}
// 8 floats (2 float4) -> one uint4 of hi bf16 and one uint4 of lo bf16.
__device__ __forceinline__ void split8(const float4 v0, const float4 v1,
                                       uint4& hi, uint4& lo)
{
    split2(v0.x, v0.y, hi.x, lo.x);
    split2(v0.z, v0.w, hi.y, lo.y);
    split2(v1.x, v1.y, hi.z, lo.z);
    split2(v1.z, v1.w, hi.w, lo.w);
}

// ---------------------------------------------------------------------------
// Kernel 0: fused prep (769 blocks). Block 0 sorts keys, builds the GEMM job
// list, and computes small L1 terms; blocks 1..256 split x; blocks 257..768
// split W1 (+ per-slice L1 partials). Wide uint4 stores (2x fewer issue
// cycles on the store path vs bf16x2 stores).
// ---------------------------------------------------------------------------
__global__ __launch_bounds__(256)
void prep_kernel(const float* __restrict__ x,
                 const float* __restrict__ W1,
                 const int*   __restrict__ keys,
                 const float* __restrict__ b1,
                 const float* __restrict__ W2,
                 const float* __restrict__ b2,
                 __nv_bfloat16* __restrict__ xhi,
                 __nv_bfloat16* __restrict__ xlo,
                 __nv_bfloat16* __restrict__ whi,
                 __nv_bfloat16* __restrict__ wlo)
{
    const int tid  = threadIdx.x;
    const int lane = tid & 31;
    const int warp = tid >> 5;
    if (blockIdx.x == 0) {
        // ---- sort: group samples by expert ----
        __shared__ int cnt[E_TASKS];
        __shared__ int off[E_TASKS];
        __shared__ int cur[E_TASKS];
        if (tid < E_TASKS) { cnt[tid] = 0; cur[tid] = 0; }
        __syncthreads();
        for (int n = tid; n < N_SAMPLES; n += 256)
            atomicAdd(&cnt[keys[n]], 1);
        __syncthreads();
        if (tid == 0) {
            int s = 0;
            int j = 0;
            for (int e = 0; e < E_TASKS; e++) {
                off[e] = s; s += cnt[e];
                int tiles = (cnt[e] + BM - 1) / BM;
                for (int m = 0; m < tiles; m++) g_jobs[j++] = (e << 16) | m;
            }
            g_njobs = j;
        }
        __syncthreads();
        if (tid < E_TASKS) { g_counts[tid] = cnt[tid]; g_offsets[tid] = off[tid]; }
        for (int n = tid; n < N_SAMPLES; n += 256) {
            int e = keys[n];
            int p = atomicAdd(&cur[e], 1);
            g_perm[off[e] + p] = n;
        }
        // ---- small L1 terms: 8 warps x 2 experts ----
#pragma unroll
        for (int k = 0; k < 2; k++) {
            int e = warp * 2 + k;
            float s = 0.f;
            for (int i = lane; i < B_MID; i += 32)
                s += fabsf(b1[e * B_MID + i]) + fabsf(W2[e * B_MID + i]);
#pragma unroll
            for (int o = 16; o > 0; o >>= 1)
                s += __shfl_xor_sync(0xffffffffu, s, o);
            if (lane == 0) g_l1small[e] = s + fabsf(b2[e]);
        }
    } else if (blockIdx.x <= 256) {
        // ---- split x: 256 blocks x 256 threads x 8 steps of 2 float4 ----
        const int blk = blockIdx.x - 1;
        const float4* src = (const float4*)x + (size_t)blk * 4096;
        uint4* dhi = (uint4*)xhi + (size_t)blk * 2048;
        uint4* dlo = (uint4*)xlo + (size_t)blk * 2048;
#pragma unroll
        for (int it = 0; it < 8; it++) {
            int i = tid + it * 256;            // output uint4 index 0..2047
            float4 v0 = src[2 * i];
            float4 v1 = src[2 * i + 1];
            uint4 hi, lo;
            split8(v0, v1, hi, lo);
            dhi[i] = hi;
            dlo[i] = lo;
        }
    } else {
        // ---- split W1 + L1 partials: 512 blocks x 8 steps of 2 float4 ----
        const int blk = blockIdx.x - 257;               // 0..511
        const float4* src = (const float4*)W1 + (size_t)blk * 4096;
        uint4* dhi = (uint4*)whi + (size_t)blk * 2048;
        uint4* dlo = (uint4*)wlo + (size_t)blk * 2048;
        float s = 0.f;
#pragma unroll
        for (int it = 0; it < 8; it++) {
            int i = tid + it * 256;
            float4 v0 = src[2 * i];
            float4 v1 = src[2 * i + 1];
            s += fabsf(v0.x) + fabsf(v0.y) + fabsf(v0.z) + fabsf(v0.w)
               + fabsf(v1.x) + fabsf(v1.y) + fabsf(v1.z) + fabsf(v1.w);
            uint4 hi, lo;
            split8(v0, v1, hi, lo);
            dhi[i] = hi;
            dlo[i] = lo;
        }
        __shared__ float red[256];
        red[tid] = s;
        __syncthreads();
        for (int st = 128; st > 0; st >>= 1) {
            if (tid < st) red[tid] += red[tid + st];
            __syncthreads();
        }
        if (tid == 0) g_l1part[blk] = red[0];
    }
}

// ---------------------------------------------------------------------------
// Tensor-core / async-copy helpers (legacy mma.sync path — tcgen05 is not
// available through this bench's compile target)
// ---------------------------------------------------------------------------
__device__ __forceinline__ uint32_t smem_u32(const void* p) {
    return (uint32_t)__cvta_generic_to_shared(p);
}
__device__ __forceinline__ void ldsm_x4(uint32_t& r0, uint32_t& r1,
                                        uint32_t& r2, uint32_t& r3, uint32_t a) {
    asm volatile("ldmatrix.sync.aligned.m8n8.x4.shared.b16 {%0,%1,%2,%3}, [%4];"
                 : "=r"(r0), "=r"(r1), "=r"(r2), "=r"(r3) : "r"(a));
}
__device__ __forceinline__ void mma_bf16(float (&d)[4], const uint32_t (&a)[4],
                                         const uint32_t (&b)[2]) {
    asm volatile("mma.sync.aligned.m16n8k16.row.col.f32.bf16.bf16.f32 "
                 "{%0,%1,%2,%3}, {%4,%5,%6,%7}, {%8,%9}, {%0,%1,%2,%3};"
                 : "+f"(d[0]), "+f"(d[1]), "+f"(d[2]), "+f"(d[3])
                 : "r"(a[0]), "r"(a[1]), "r"(a[2]), "r"(a[3]),
                   "r"(b[0]), "r"(b[1]));
}
__device__ __forceinline__ void cp16(uint32_t dst, const void* src, bool valid) {
    int sz = valid ? 16 : 0;   // sz=0 -> zero-fill
    asm volatile("cp.async.cg.shared.global [%0], [%1], 16, %2;"
                 :: "r"(dst), "l"(src), "r"(sz));
}
__device__ __forceinline__ void cp_commit() {
    asm volatile("cp.async.commit_group;");
}
__device__ __forceinline__ void cp_wait0() {
    asm volatile("cp.async.wait_group 0;");
}

// ---------------------------------------------------------------------------
// Kernel 2: grouped bf16x3 GEMM + fused layer-2 partial, job-list driven.
// h = relu(Xg @ W1[e]^T + b1[e]); p[n][nblk] = h(128 cols) . W2[e] slice
// Block tile 64x128x64, 8 warps (2m x 4n), warp tile 32x32, 2-stage.
// Mainloop/epilogue identical to the measured-best R11/R13/R14 configuration.
// ---------------------------------------------------------------------------
__global__ __launch_bounds__(NTHREADS, 2)
void gemm1_kernel(const float* __restrict__ b1, const float* __restrict__ W2)
{
    if ((int)blockIdx.y >= g_njobs) return;
    const int job = g_jobs[blockIdx.y];
    const int e   = job >> 16;
    const int m0  = (job & 0xffff) * BM;
    const int cnt = g_counts[e];
    const int off = g_offsets[e];
    const int nblk = blockIdx.x;
    const int n0  = nblk * BN;

    extern __shared__ __align__(16) char smem_dyn[];
    int*   rows  = (int*)(smem_dyn + OFF_ROWS);
    float* spart = (float*)(smem_dyn + OFF_PART);   // [64][4]

    const int tid  = threadIdx.x;
    const int lane = tid & 31;
    const int warp = tid >> 5;
    const int wm   = warp >> 2;  // 0..1
    const int wn   = warp & 3;   // 0..3

    if (tid < BM) {
        int m = m0 + tid;
        rows[tid] = (m < cnt) ? g_perm[off + m] : -1;
    }
    __syncthreads();

    const uint32_t sbase = smem_u32(smem_dyn);

    // ---- per-thread cp.async slots: chunk c of 16B, rows r0+32q ----
    const int c  = tid & 7;
    const int r0 = tid >> 3;                         // 0..31
    const uint32_t cpoff = (uint32_t)((c ^ (r0 & 7)) * 16);   // (r&7)==(r0&7)
    uint32_t dstA[2], dstB[4];
    const __nv_bfloat16 *pAh[2], *pAl[2], *pBh[4], *pBl[4];
    bool vA[2];
#pragma unroll
    for (int q = 0; q < 2; q++) {
        int r = r0 + 32 * q;
        dstA[q] = (uint32_t)r * 128u + cpoff;
        int gr = rows[r];
        vA[q] = gr >= 0;
        pAh[q] = g_xhi + (size_t)(vA[q] ? gr : 0) * D_IN + c * 8;
        pAl[q] = g_xlo + (size_t)(vA[q] ? gr : 0) * D_IN + c * 8;
    }
#pragma unroll
    for (int q = 0; q < 4; q++) {
        int r = r0 + 32 * q;
        dstB[q] = (uint32_t)r * 128u + cpoff;
        size_t wb = (size_t)(e * B_MID + n0 + r) * D_IN + c * 8;
        pBh[q] = g_whi + wb;
        pBl[q] = g_wlo + wb;
    }

    // ---- per-warp fragment addressing constants ----
    uint32_t aRowBase[2], aSw[2];
#pragma unroll
    for (int i = 0; i < 2; i++) {
        int arow = wm * 32 + i * 16 + (lane & 15);
        aRowBase[i] = (uint32_t)arow * 128u;
        aSw[i] = (uint32_t)(arow & 7);
    }
    const uint32_t aD = (uint32_t)(lane >> 4);
    uint32_t bPairBase[2];
#pragma unroll
    for (int p = 0; p < 2; p++) {
        int brow = wn * 32 + p * 16 + ((lane >> 4) & 1) * 8 + (lane & 7);
        bPairBase[p] = (uint32_t)brow * 128u;
    }
    const uint32_t bSw = (uint32_t)(lane & 7);
    const uint32_t bD  = (uint32_t)((lane >> 3) & 1);

    float acc[2][4][4];
#pragma unroll
    for (int i = 0; i < 2; i++)
#pragma unroll
        for (int j = 0; j < 4; j++)
#pragma unroll
            for (int q = 0; q < 4; q++) acc[i][j][q] = 0.f;

#define TISSUE(s, kbase)                                                      \
    do {                                                                      \
        uint32_t sb_ = sbase + (s) * STAGE_B;                                 \
        _Pragma("unroll")                                                     \
        for (int q = 0; q < 2; q++) {                                         \
            cp16(sb_ + dstA[q],         pAh[q] + (kbase), vA[q]);             \
            cp16(sb_ + ST_AL + dstA[q], pAl[q] + (kbase), vA[q]);             \
        }                                                                     \
        _Pragma("unroll")                                                     \
        for (int q = 0; q < 4; q++) {                                         \
            cp16(sb_ + ST_BH + dstB[q], pBh[q] + (kbase), true);              \
            cp16(sb_ + ST_BL + dstB[q], pBl[q] + (kbase), true);              \
        }                                                                     \
    } while (0)

#define COMPUTE_T(t)                                                          \
    do {                                                                      \
        uint32_t bhf[4][2], blf[4][2];                                        \
        _Pragma("unroll")                                                     \
        for (int p = 0; p < 2; p++) {                                         \
            uint32_t o = bPairBase[p] + ((((2u * (t)) | bD) ^ bSw) << 4);     \
            ldsm_x4(bhf[2*p][0], bhf[2*p][1], bhf[2*p+1][0], bhf[2*p+1][1],   \
                    bH + o);                                                  \
            ldsm_x4(blf[2*p][0], blf[2*p][1], blf[2*p+1][0], blf[2*p+1][1],   \
                    bL + o);                                                  \
        }                                                                     \
        _Pragma("unroll")                                                     \
        for (int i = 0; i < 2; i++) {                                         \
            uint32_t o = aRowBase[i] + ((((2u * (t)) | aD) ^ aSw[i]) << 4);   \
            uint32_t ah[4], al[4];                                            \
            ldsm_x4(ah[0], ah[1], ah[2], ah[3], aH + o);                      \
            ldsm_x4(al[0], al[1], al[2], al[3], aL + o);                      \
            _Pragma("unroll")                                                 \
            for (int j = 0; j < 4; j++) {                                     \
                mma_bf16(acc[i][j], ah, bhf[j]);                              \
                mma_bf16(acc[i][j], ah, blf[j]);                              \
                mma_bf16(acc[i][j], al, bhf[j]);                              \
            }                                                                 \
        }                                                                     \
    } while (0)

    TISSUE(0, 0);
    cp_commit();

    for (int it = 0; it < NITER; ++it) {
        const int s = it & 1;
        cp_wait0();          // stage s data landed
        __syncthreads();     // visible to all; prior compute done before issue

        const uint32_t aH = sbase + s * STAGE_B;
        const uint32_t aL = aH + ST_AL;
        const uint32_t bH = aH + ST_BH;
        const uint32_t bL = aH + ST_BL;

        COMPUTE_T(0);
        if (it + 1 < NITER) {          // issue prefetch after t=0: spreads LSU
            TISSUE(1 - s, (it + 1) * BK);
            cp_commit();
        }
        COMPUTE_T(1);
        COMPUTE_T(2);
        COMPUTE_T(3);
    }
#undef TISSUE
#undef COMPUTE_T

    // ---- fused epilogue: h = relu(acc+b1); partial = h . W2-slice ----
    const int g  = lane >> 2;
    const int cq = lane & 3;
    float p[2][2];   // [i][row-half]
#pragma unroll
    for (int i = 0; i < 2; i++) { p[i][0] = 0.f; p[i][1] = 0.f; }

#pragma unroll
    for (int j = 0; j < 4; j++) {
        int gcol = n0 + wn * 32 + j * 8 + 2 * cq;
        float2 bb = *(const float2*)(b1 + e * B_MID + gcol);
        float2 ww = *(const float2*)(W2 + e * B_MID + gcol);
#pragma unroll
        for (int i = 0; i < 2; i++) {
            float h0 = fmaxf(acc[i][j][0] + bb.x, 0.f);
            float h1 = fmaxf(acc[i][j][1] + bb.y, 0.f);
            float h2 = fmaxf(acc[i][j][2] + bb.x, 0.f);
            float h3 = fmaxf(acc[i][j][3] + bb.y, 0.f);
            p[i][0] = fmaf(h0, ww.x, fmaf(h1, ww.y, p[i][0]));
            p[i][1] = fmaf(h2, ww.x, fmaf(h3, ww.y, p[i][1]));
        }
    }
    // reduce across the 4 lanes of each quad (fixed butterfly order)
#pragma unroll
    for (int i = 0; i < 2; i++)
#pragma unroll
        for (int hh = 0; hh < 2; hh++) {
            p[i][hh] += __shfl_xor_sync(0xffffffffu, p[i][hh], 1);
            p[i][hh] += __shfl_xor_sync(0xffffffffu, p[i][hh], 2);
        }
    if (cq == 0) {
#pragma unroll
        for (int i = 0; i < 2; i++) {
            int row0 = wm * 32 + i * 16 + g;
            spart[row0 * 4 + wn]       = p[i][0];
            spart[(row0 + 8) * 4 + wn] = p[i][1];
        }
    }
    __syncthreads();
    if (tid < BM && (m0 + tid) < cnt) {
        int r = rows[tid];
        float v = spart[tid * 4 + 0] + spart[tid * 4 + 1]
                + spart[tid * 4 + 2] + spart[tid * 4 + 3];
        g_part[(size_t)r * 4 + nblk] = v;
    }
}

// ---------------------------------------------------------------------------
// Kernel 3: finalize. Blocks 0..15: out[n] from layer-2 partials.
// Block 16: L1 scalar from g_l1part + g_l1small (fixed-order reduction).
// ---------------------------------------------------------------------------
__global__ void final_kernel(const int* __restrict__ keys,
                             const float* __restrict__ b2,
                             float* __restrict__ out, int out_size)
{
    if (blockIdx.x < 16) {
        int n = blockIdx.x * 256 + threadIdx.x;
        float4 pv = *(const float4*)(g_part + (size_t)n * 4);
        out[n] = pv.x + pv.y + pv.z + pv.w + b2[keys[n]];
    } else if (threadIdx.x < 32 && out_size > N_SAMPLES) {
        int lane = threadIdx.x;
        float tot = 0.f;
        for (int e = 0; e < E_TASKS; e++) {
            float pe = g_l1part[e * L1_SLICES + lane];   // 32 lanes = 32 slices
#pragma unroll
            for (int o = 16; o > 0; o >>= 1)
                pe += __shfl_xor_sync(0xffffffffu, pe, o);
            if (lane == 0) {
                pe += g_l1small[e];
                tot += (float)g_counts[e] * pe;
            }
        }
        if (lane == 0) out[N_SAMPLES] = L1_LAMBDA * tot;
    }
}

// ---------------------------------------------------------------------------
extern "C" void kernel_launch(void* const* d_in, const int* in_sizes, int n_in,
                              void* d_out, int out_size)
{
    const float* x    = (const float*)d_in[0];
    const int*   keys = (const int*)  d_in[1];
    const float* W1   = (const float*)d_in[2];
    const float* b1   = (const float*)d_in[3];
    const float* W2   = (const float*)d_in[4];
    const float* b2   = (const float*)d_in[5];
    float* out = (float*)d_out;

    cudaFuncSetAttribute(gemm1_kernel,
                         cudaFuncAttributeMaxDynamicSharedMemorySize,
                         SMEM_BYTES);

    __nv_bfloat16 *xhi, *xlo, *whi, *wlo;
    cudaGetSymbolAddress((void**)&xhi, g_xhi);
    cudaGetSymbolAddress((void**)&xlo, g_xlo);
    cudaGetSymbolAddress((void**)&whi, g_whi);
    cudaGetSymbolAddress((void**)&wlo, g_wlo);

    prep_kernel<<<769, 256>>>(x, W1, keys, b1, W2, b2, xhi, xlo, whi, wlo);

    dim3 grid(B_MID / BN, MAXJOBS);   // (4, 80) job-list driven
    gemm1_kernel<<<grid, NTHREADS, SMEM_BYTES>>>(b1, W2);

    final_kernel<<<17, 256>>>(keys, b2, out, out_size);
}

// round 16
// speedup vs baseline: 1.0611x; 1.0611x over previous
#include <cuda_runtime.h>
#include <cuda_bf16.h>
#include <cstdint>

// Problem constants (fixed by the reference)
#define N_SAMPLES 4096
#define D_IN      1024
#define B_MID     512
#define E_TASKS   16
#define L1_LAMBDA 1e-4f
#define L1_SLICES 32   // W1 slices per expert (512 W-blocks in prep)

// GEMM tiling: block 64(M) x 128(N) x 64(K), 8 warps (2m x 4n), 2-stage
#define BM 64
#define BN 128
#define BK 64
#define NTHREADS 256
#define NITER (D_IN / BK)   // 16
#define MAXJOBS 80          // sum_e ceil(cnt_e/BM) <= 4096/64 + 16

// Dynamic smem (bytes). Stage = {Ah 8K, Al 8K, Bh 16K, Bl 16K} = 48K.
// Rows are 128B wide (64 bf16), SW128 swizzle chunk' = c ^ (row&7).
#define ST_AL 8192
#define ST_BH 16384
#define ST_BL 32768
#define STAGE_B 49152
#define OFF_ROWS  (2 * STAGE_B)            // 64 ints
#define OFF_PART  (OFF_ROWS + 256)         // 64 x 4 floats
#define SMEM_BYTES (OFF_PART + 1024)       // 99584

// Static device scratch (no allocations allowed; zero-initialized at load)
__device__ __nv_bfloat16 g_xhi[(size_t)N_SAMPLES * D_IN];
__device__ __nv_bfloat16 g_xlo[(size_t)N_SAMPLES * D_IN];
__device__ __nv_bfloat16 g_whi[(size_t)E_TASKS * B_MID * D_IN];
__device__ __nv_bfloat16 g_wlo[(size_t)E_TASKS * B_MID * D_IN];
__device__ float g_part[(size_t)N_SAMPLES * 4];   // layer-2 partials per n-block
__device__ int   g_perm[N_SAMPLES];
__device__ int   g_counts[E_TASKS];
__device__ int   g_offsets[E_TASKS];
__device__ int   g_jobs[MAXJOBS];                 // packed (e<<16)|mtile
__device__ int   g_njobs;
__device__ float g_l1part[E_TASKS * L1_SLICES];

// ---------------------------------------------------------------------------
// Kernel 0: fused prep (769 blocks). Block 0: sort keys + build job list
// ONLY (keeps the serial block short — it bounds the kernel). Blocks 1..256
// split x; blocks 257..768 split W1 (+ per-slice L1 partials). Scalar bf16x2
// stores (measured-best R14 form; wide uint4 stores regressed in R15).
// ---------------------------------------------------------------------------
__global__ __launch_bounds__(256)
void prep_kernel(const float* __restrict__ x,
                 const float* __restrict__ W1,
                 const int*   __restrict__ keys,
                 __nv_bfloat16* __restrict__ xhi,
                 __nv_bfloat16* __restrict__ xlo,
                 __nv_bfloat16* __restrict__ whi,
                 __nv_bfloat16* __restrict__ wlo)
{
    const int tid = threadIdx.x;
    if (blockIdx.x == 0) {
        // ---- sort: group samples by expert; emit compacted job list ----
        __shared__ int cnt[E_TASKS];
        __shared__ int off[E_TASKS];
        __shared__ int cur[E_TASKS];
        if (tid < E_TASKS) { cnt[tid] = 0; cur[tid] = 0; }
        __syncthreads();
        for (int n = tid; n < N_SAMPLES; n += 256)
            atomicAdd(&cnt[keys[n]], 1);
        __syncthreads();
        if (tid == 0) {
            int s = 0;
            int j = 0;
            for (int e = 0; e < E_TASKS; e++) {
                off[e] = s; s += cnt[e];
                int tiles = (cnt[e] + BM - 1) / BM;
                for (int m = 0; m < tiles; m++) g_jobs[j++] = (e << 16) | m;
            }
            g_njobs = j;
        }
        __syncthreads();
        if (tid < E_TASKS) { g_counts[tid] = cnt[tid]; g_offsets[tid] = off[tid]; }
        for (int n = tid; n < N_SAMPLES; n += 256) {
            int e = keys[n];
            int p = atomicAdd(&cur[e], 1);
            g_perm[off[e] + p] = n;
        }
    } else if (blockIdx.x <= 256) {
        // ---- split x: 256 blocks x 256 threads x 16 float4 ----
        const int blk = blockIdx.x - 1;
        const size_t base = (size_t)blk * 4096;         // float4 units
        const float4* src = (const float4*)x + base;
#pragma unroll
        for (int it = 0; it < 16; it++) {
            int i = tid + it * 256;
            float4 v = src[i];
            __nv_bfloat16 h0 = __float2bfloat16_rn(v.x);
            __nv_bfloat16 h1 = __float2bfloat16_rn(v.y);
            __nv_bfloat16 h2 = __float2bfloat16_rn(v.z);
            __nv_bfloat16 h3 = __float2bfloat16_rn(v.w);
            size_t g = base + i;
            ((__nv_bfloat162*)xhi)[2 * g + 0] = __nv_bfloat162(h0, h1);
            ((__nv_bfloat162*)xhi)[2 * g + 1] = __nv_bfloat162(h2, h3);
            ((__nv_bfloat162*)xlo)[2 * g + 0] = __nv_bfloat162(
                __float2bfloat16_rn(v.x - __bfloat162float(h0)),
                __float2bfloat16_rn(v.y - __bfloat162float(h1)));
            ((__nv_bfloat162*)xlo)[2 * g + 1] = __nv_bfloat162(
                __float2bfloat16_rn(v.z - __bfloat162float(h2)),
                __float2bfloat16_rn(v.w - __bfloat162float(h3)));
        }
    } else {
        // ---- split W1 + L1 partials: 512 blocks ----
        const int blk = blockIdx.x - 257;               // 0..511
        const int C4  = (B_MID * D_IN) / L1_SLICES / 4; // 4096 float4
        const size_t base = (size_t)blk * C4;
        const float4* src = (const float4*)W1 + base;
        float s = 0.f;
        for (int i = tid; i < C4; i += 256) {
            float4 v = src[i];
            s += fabsf(v.x) + fabsf(v.y) + fabsf(v.z) + fabsf(v.w);
            __nv_bfloat16 h0 = __float2bfloat16_rn(v.x);
            __nv_bfloat16 h1 = __float2bfloat16_rn(v.y);
            __nv_bfloat16 h2 = __float2bfloat16_rn(v.z);
            __nv_bfloat16 h3 = __float2bfloat16_rn(v.w);
            size_t g = base + i;
            ((__nv_bfloat162*)whi)[2 * g + 0] = __nv_bfloat162(h0, h1);
            ((__nv_bfloat162*)whi)[2 * g + 1] = __nv_bfloat162(h2, h3);
            ((__nv_bfloat162*)wlo)[2 * g + 0] = __nv_bfloat162(
                __float2bfloat16_rn(v.x - __bfloat162float(h0)),
                __float2bfloat16_rn(v.y - __bfloat162float(h1)));
            ((__nv_bfloat162*)wlo)[2 * g + 1] = __nv_bfloat162(
                __float2bfloat16_rn(v.z - __bfloat162float(h2)),
                __float2bfloat16_rn(v.w - __bfloat162float(h3)));
        }
        __shared__ float red[256];
        red[tid] = s;
        __syncthreads();
        for (int st = 128; st > 0; st >>= 1) {
            if (tid < st) red[tid] += red[tid + st];
            __syncthreads();
        }
        if (tid == 0) g_l1part[blk] = red[0];
    }
}

// ---------------------------------------------------------------------------
// Tensor-core / async-copy helpers (legacy mma.sync path — tcgen05 is not
// available through this bench's compile target)
// ---------------------------------------------------------------------------
__device__ __forceinline__ uint32_t smem_u32(const void* p) {
    return (uint32_t)__cvta_generic_to_shared(p);
}
__device__ __forceinline__ void ldsm_x4(uint32_t& r0, uint32_t& r1,
                                        uint32_t& r2, uint32_t& r3, uint32_t a) {
    asm volatile("ldmatrix.sync.aligned.m8n8.x4.shared.b16 {%0,%1,%2,%3}, [%4];"
                 : "=r"(r0), "=r"(r1), "=r"(r2), "=r"(r3) : "r"(a));
}
__device__ __forceinline__ void mma_bf16(float (&d)[4], const uint32_t (&a)[4],
                                         const uint32_t (&b)[2]) {
    asm volatile("mma.sync.aligned.m16n8k16.row.col.f32.bf16.bf16.f32 "
                 "{%0,%1,%2,%3}, {%4,%5,%6,%7}, {%8,%9}, {%0,%1,%2,%3};"
                 : "+f"(d[0]), "+f"(d[1]), "+f"(d[2]), "+f"(d[3])
                 : "r"(a[0]), "r"(a[1]), "r"(a[2]), "r"(a[3]),
                   "r"(b[0]), "r"(b[1]));
}
__device__ __forceinline__ void cp16(uint32_t dst, const void* src, bool valid) {
    int sz = valid ? 16 : 0;   // sz=0 -> zero-fill
    asm volatile("cp.async.cg.shared.global [%0], [%1], 16, %2;"
                 :: "r"(dst), "l"(src), "r"(sz));
}
__device__ __forceinline__ void cp_commit() {
    asm volatile("cp.async.commit_group;");
}
__device__ __forceinline__ void cp_wait0() {
    asm volatile("cp.async.wait_group 0;");
}

// ---------------------------------------------------------------------------
// Kernel 2: grouped bf16x3 GEMM + fused layer-2 partial, job-list driven.
// h = relu(Xg @ W1[e]^T + b1[e]); p[n][nblk] = h(128 cols) . W2[e] slice
// Block tile 64x128x64, 8 warps (2m x 4n), warp tile 32x32, 2-stage.
// Mainloop/epilogue identical to the measured-best R11/R13/R14 configuration.
// ---------------------------------------------------------------------------
__global__ __launch_bounds__(NTHREADS, 2)
void gemm1_kernel(const float* __restrict__ b1, const float* __restrict__ W2)
{
    if ((int)blockIdx.y >= g_njobs) return;
    const int job = g_jobs[blockIdx.y];
    const int e   = job >> 16;
    const int m0  = (job & 0xffff) * BM;
    const int cnt = g_counts[e];
    const int off = g_offsets[e];
    const int nblk = blockIdx.x;
    const int n0  = nblk * BN;

    extern __shared__ __align__(16) char smem_dyn[];
    int*   rows  = (int*)(smem_dyn + OFF_ROWS);
    float* spart = (float*)(smem_dyn + OFF_PART);   // [64][4]

    const int tid  = threadIdx.x;
    const int lane = tid & 31;
    const int warp = tid >> 5;
    const int wm   = warp >> 2;  // 0..1
    const int wn   = warp & 3;   // 0..3

    if (tid < BM) {
        int m = m0 + tid;
        rows[tid] = (m < cnt) ? g_perm[off + m] : -1;
    }
    __syncthreads();

    const uint32_t sbase = smem_u32(smem_dyn);

    // ---- per-thread cp.async slots: chunk c of 16B, rows r0+32q ----
    const int c  = tid & 7;
    const int r0 = tid >> 3;                         // 0..31
    const uint32_t cpoff = (uint32_t)((c ^ (r0 & 7)) * 16);   // (r&7)==(r0&7)
    uint32_t dstA[2], dstB[4];
    const __nv_bfloat16 *pAh[2], *pAl[2], *pBh[4], *pBl[4];
    bool vA[2];
#pragma unroll
    for (int q = 0; q < 2; q++) {
        int r = r0 + 32 * q;
        dstA[q] = (uint32_t)r * 128u + cpoff;
        int gr = rows[r];
        vA[q] = gr >= 0;
        pAh[q] = g_xhi + (size_t)(vA[q] ? gr : 0) * D_IN + c * 8;
        pAl[q] = g_xlo + (size_t)(vA[q] ? gr : 0) * D_IN + c * 8;
    }
#pragma unroll
    for (int q = 0; q < 4; q++) {
        int r = r0 + 32 * q;
        dstB[q] = (uint32_t)r * 128u + cpoff;
        size_t wb = (size_t)(e * B_MID + n0 + r) * D_IN + c * 8;
        pBh[q] = g_whi + wb;
        pBl[q] = g_wlo + wb;
    }

    // ---- per-warp fragment addressing constants ----
    uint32_t aRowBase[2], aSw[2];
#pragma unroll
    for (int i = 0; i < 2; i++) {
        int arow = wm * 32 + i * 16 + (lane & 15);
        aRowBase[i] = (uint32_t)arow * 128u;
        aSw[i] = (uint32_t)(arow & 7);
    }
    const uint32_t aD = (uint32_t)(lane >> 4);
    uint32_t bPairBase[2];
#pragma unroll
    for (int p = 0; p < 2; p++) {
        int brow = wn * 32 + p * 16 + ((lane >> 4) & 1) * 8 + (lane & 7);
        bPairBase[p] = (uint32_t)brow * 128u;
    }
    const uint32_t bSw = (uint32_t)(lane & 7);
    const uint32_t bD  = (uint32_t)((lane >> 3) & 1);

    float acc[2][4][4];
#pragma unroll
    for (int i = 0; i < 2; i++)
#pragma unroll
        for (int j = 0; j < 4; j++)
#pragma unroll
            for (int q = 0; q < 4; q++) acc[i][j][q] = 0.f;

#define TISSUE(s, kbase)                                                      \
    do {                                                                      \
        uint32_t sb_ = sbase + (s) * STAGE_B;                                 \
        _Pragma("unroll")                                                     \
        for (int q = 0; q < 2; q++) {                                         \
            cp16(sb_ + dstA[q],         pAh[q] + (kbase), vA[q]);             \
            cp16(sb_ + ST_AL + dstA[q], pAl[q] + (kbase), vA[q]);             \
        }                                                                     \
        _Pragma("unroll")                                                     \
        for (int q = 0; q < 4; q++) {                                         \
            cp16(sb_ + ST_BH + dstB[q], pBh[q] + (kbase), true);              \
            cp16(sb_ + ST_BL + dstB[q], pBl[q] + (kbase), true);              \
        }                                                                     \
    } while (0)

#define COMPUTE_T(t)                                                          \
    do {                                                                      \
        uint32_t bhf[4][2], blf[4][2];                                        \
        _Pragma("unroll")                                                     \
        for (int p = 0; p < 2; p++) {                                         \
            uint32_t o = bPairBase[p] + ((((2u * (t)) | bD) ^ bSw) << 4);     \
            ldsm_x4(bhf[2*p][0], bhf[2*p][1], bhf[2*p+1][0], bhf[2*p+1][1],   \
                    bH + o);                                                  \
            ldsm_x4(blf[2*p][0], blf[2*p][1], blf[2*p+1][0], blf[2*p+1][1],   \
                    bL + o);                                                  \
        }                                                                     \
        _Pragma("unroll")                                                     \
        for (int i = 0; i < 2; i++) {                                         \
            uint32_t o = aRowBase[i] + ((((2u * (t)) | aD) ^ aSw[i]) << 4);   \
            uint32_t ah[4], al[4];                                            \
            ldsm_x4(ah[0], ah[1], ah[2], ah[3], aH + o);                      \
            ldsm_x4(al[0], al[1], al[2], al[3], aL + o);                      \
            _Pragma("unroll")                                                 \
            for (int j = 0; j < 4; j++) {                                     \
                mma_bf16(acc[i][j], ah, bhf[j]);                              \
                mma_bf16(acc[i][j], ah, blf[j]);                              \
                mma_bf16(acc[i][j], al, bhf[j]);                              \
            }                                                                 \
        }                                                                     \
    } while (0)

    TISSUE(0, 0);
    cp_commit();

    for (int it = 0; it < NITER; ++it) {
        const int s = it & 1;
        cp_wait0();          // stage s data landed
        __syncthreads();     // visible to all; prior compute done before issue

        const uint32_t aH = sbase + s * STAGE_B;
        const uint32_t aL = aH + ST_AL;
        const uint32_t bH = aH + ST_BH;
        const uint32_t bL = aH + ST_BL;

        COMPUTE_T(0);
        if (it + 1 < NITER) {          // issue prefetch after t=0: spreads LSU
            TISSUE(1 - s, (it + 1) * BK);
            cp_commit();
        }
        COMPUTE_T(1);
        COMPUTE_T(2);
        COMPUTE_T(3);
    }
#undef TISSUE
#undef COMPUTE_T

    // ---- fused epilogue: h = relu(acc+b1); partial = h . W2-slice ----
    const int g  = lane >> 2;
    const int cq = lane & 3;
    float p[2][2];   // [i][row-half]
#pragma unroll
    for (int i = 0; i < 2; i++) { p[i][0] = 0.f; p[i][1] = 0.f; }

#pragma unroll
    for (int j = 0; j < 4; j++) {
        int gcol = n0 + wn * 32 + j * 8 + 2 * cq;
        float2 bb = *(const float2*)(b1 + e * B_MID + gcol);
        float2 ww = *(const float2*)(W2 + e * B_MID + gcol);
#pragma unroll
        for (int i = 0; i < 2; i++) {
            float h0 = fmaxf(acc[i][j][0] + bb.x, 0.f);
            float h1 = fmaxf(acc[i][j][1] + bb.y, 0.f);
            float h2 = fmaxf(acc[i][j][2] + bb.x, 0.f);
            float h3 = fmaxf(acc[i][j][3] + bb.y, 0.f);
            p[i][0] = fmaf(h0, ww.x, fmaf(h1, ww.y, p[i][0]));
            p[i][1] = fmaf(h2, ww.x, fmaf(h3, ww.y, p[i][1]));
        }
    }
    // reduce across the 4 lanes of each quad (fixed butterfly order)
#pragma unroll
    for (int i = 0; i < 2; i++)
#pragma unroll
        for (int hh = 0; hh < 2; hh++) {
            p[i][hh] += __shfl_xor_sync(0xffffffffu, p[i][hh], 1);
            p[i][hh] += __shfl_xor_sync(0xffffffffu, p[i][hh], 2);
        }
    if (cq == 0) {
#pragma unroll
        for (int i = 0; i < 2; i++) {
            int row0 = wm * 32 + i * 16 + g;
            spart[row0 * 4 + wn]       = p[i][0];
            spart[(row0 + 8) * 4 + wn] = p[i][1];
        }
    }
    __syncthreads();
    if (tid < BM && (m0 + tid) < cnt) {
        int r = rows[tid];
        float v = spart[tid * 4 + 0] + spart[tid * 4 + 1]
                + spart[tid * 4 + 2] + spart[tid * 4 + 3];
        g_part[(size_t)r * 4 + nblk] = v;
    }
}

// ---------------------------------------------------------------------------
// Kernel 3: finalize. Blocks 0..15: out[n] from layer-2 partials.
// Block 16: L1 scalar — small terms (b1, W2, b2) computed here (8 warps x 2
// experts; each lane folds its g_l1part slice into the same fixed butterfly).
// ---------------------------------------------------------------------------
__global__ void final_kernel(const int* __restrict__ keys,
                             const float* __restrict__ b1,
                             const float* __restrict__ W2,
                             const float* __restrict__ b2,
                             float* __restrict__ out, int out_size)
{
    const int tid = threadIdx.x;
    if (blockIdx.x < 16) {
        int n = blockIdx.x * 256 + tid;
        float4 pv = *(const float4*)(g_part + (size_t)n * 4);
        out[n] = pv.x + pv.y + pv.z + pv.w + b2[keys[n]];
    } else if (out_size > N_SAMPLES) {
        __shared__ float l1s[E_TASKS];
        int warp = tid >> 5, lane = tid & 31;
#pragma unroll
        for (int k = 0; k < 2; k++) {
            int e = warp * 2 + k;
            float s = g_l1part[e * L1_SLICES + lane];   // 32 lanes = 32 slices
            for (int i = lane; i < B_MID; i += 32)
                s += fabsf(b1[e * B_MID + i]) + fabsf(W2[e * B_MID + i]);
#pragma unroll
            for (int o = 16; o > 0; o >>= 1)
                s += __shfl_xor_sync(0xffffffffu, s, o);
            if (lane == 0) l1s[e] = s + fabsf(b2[e]);
        }
        __syncthreads();
        if (tid == 0) {
            float tot = 0.f;
            for (int e = 0; e < E_TASKS; e++)
                tot += (float)g_counts[e] * l1s[e];
            out[N_SAMPLES] = L1_LAMBDA * tot;
        }
    }
}

// ---------------------------------------------------------------------------
extern "C" void kernel_launch(void* const* d_in, const int* in_sizes, int n_in,
                              void* d_out, int out_size)
{
    const float* x    = (const float*)d_in[0];
    const int*   keys = (const int*)  d_in[1];
    const float* W1   = (const float*)d_in[2];
    const float* b1   = (const float*)d_in[3];
    const float* W2   = (const float*)d_in[4];
    const float* b2   = (const float*)d_in[5];
    float* out = (float*)d_out;

    cudaFuncSetAttribute(gemm1_kernel,
                         cudaFuncAttributeMaxDynamicSharedMemorySize,
                         SMEM_BYTES);

    __nv_bfloat16 *xhi, *xlo, *whi, *wlo;
    cudaGetSymbolAddress((void**)&xhi, g_xhi);
    cudaGetSymbolAddress((void**)&xlo, g_xlo);
    cudaGetSymbolAddress((void**)&whi, g_whi);
    cudaGetSymbolAddress((void**)&wlo, g_wlo);

    prep_kernel<<<769, 256>>>(x, W1, keys, xhi, xlo, whi, wlo);

    dim3 grid(B_MID / BN, MAXJOBS);   // (4, 80) job-list driven
    gemm1_kernel<<<grid, NTHREADS, SMEM_BYTES>>>(b1, W2);

    final_kernel<<<17, 256>>>(keys, b1, W2, b2, out, out_size);
}

// round 17
// speedup vs baseline: 1.0648x; 1.0034x over previous
#include <cuda_runtime.h>
#include <cuda_bf16.h>
#include <cstdint>

// Problem constants (fixed by the reference)
#define N_SAMPLES 4096
#define D_IN      1024
#define B_MID     512
#define E_TASKS   16
#define L1_LAMBDA 1e-4f
#define L1_SLICES 32   // W1 slices per expert (512 W-blocks in prep)

// GEMM tiling: block 64(M) x 128(N) x 64(K), 8 warps (2m x 4n), 2-stage
#define BM 64
#define BN 128
#define BK 64
#define NTHREADS 256
#define NITER (D_IN / BK)   // 16
#define MAXJOBS 80          // sum_e ceil(cnt_e/BM) <= 4096/64 + 16

// Dynamic smem (bytes). Stage = {Ah 8K, Al 8K, Bh 16K, Bl 16K} = 48K.
// Rows are 128B wide (64 bf16), SW128 swizzle chunk' = c ^ (row&7).
#define ST_AL 8192
#define ST_BH 16384
#define ST_BL 32768
#define STAGE_B 49152
#define OFF_ROWS  (2 * STAGE_B)            // 64 ints
#define OFF_PART  (OFF_ROWS + 256)         // 64 x 4 floats
#define SMEM_BYTES (OFF_PART + 1024)       // 99584

// Static device scratch (no allocations allowed; zero-initialized at load)
__device__ __nv_bfloat16 g_xhi[(size_t)N_SAMPLES * D_IN];
__device__ __nv_bfloat16 g_xlo[(size_t)N_SAMPLES * D_IN];
__device__ __nv_bfloat16 g_whi[(size_t)E_TASKS * B_MID * D_IN];
__device__ __nv_bfloat16 g_wlo[(size_t)E_TASKS * B_MID * D_IN];
__device__ float g_part[(size_t)N_SAMPLES * 4];   // layer-2 partials per n-block
__device__ int   g_perm[N_SAMPLES];
__device__ int   g_counts[E_TASKS];
__device__ int   g_offsets[E_TASKS];
__device__ int   g_jobs[MAXJOBS];                 // packed (e<<16)|mtile
__device__ int   g_njobs;
__device__ float g_l1part[E_TASKS * L1_SLICES];

// ---------------------------------------------------------------------------
// Packed bf16 conversion helpers (cvt.rn.bf16x2.f32: converts+packs 2 floats
// in ONE instruction; same rn rounding as __float2bfloat16_rn).
// Result word = {hi half: first src, lo half: second src}.
// ---------------------------------------------------------------------------
__device__ __forceinline__ uint32_t cvt2_bf16(float hi, float lo) {
    uint32_t r;
    asm("cvt.rn.bf16x2.f32 %0, %1, %2;" : "=r"(r) : "f"(hi), "f"(lo));
    return r;
}
__device__ __forceinline__ float bf16lo_f(uint32_t w) {   // low bf16 -> f32
    return __uint_as_float(w << 16);
}
__device__ __forceinline__ float bf16hi_f(uint32_t w) {   // high bf16 -> f32
    return __uint_as_float(w & 0xffff0000u);
}
// Split a float4 into packed hi words (h01,h23) and lo-residual words (l01,l23).
// Memory layout: element k at bf16 slot k -> word0 = {hi:y, lo:x}, word1 = {hi:w, lo:z}.
__device__ __forceinline__ void split4(const float4 v, uint2& hw, uint2& lw) {
    uint32_t h01 = cvt2_bf16(v.y, v.x);
    uint32_t h23 = cvt2_bf16(v.w, v.z);
    float rx = v.x - bf16lo_f(h01);
    float ry = v.y - bf16hi_f(h01);
    float rz = v.z - bf16lo_f(h23);
    float rw = v.w - bf16hi_f(h23);
    hw = make_uint2(h01, h23);
    lw = make_uint2(cvt2_bf16(ry, rx), cvt2_bf16(rw, rz));
}

// ---------------------------------------------------------------------------
// Kernel 0: fused prep (769 blocks). Block 0: sort keys + build job list
// ONLY (keeps the serial block short — it bounds the kernel). Blocks 1..256
// split x; blocks 257..768 split W1 (+ per-slice L1 partials). Same 16x
// float4-per-thread structure as the measured-best R16; packed converts.
// ---------------------------------------------------------------------------
__global__ __launch_bounds__(256)
void prep_kernel(const float* __restrict__ x,
                 const float* __restrict__ W1,
                 const int*   __restrict__ keys,
                 __nv_bfloat16* __restrict__ xhi,
                 __nv_bfloat16* __restrict__ xlo,
                 __nv_bfloat16* __restrict__ whi,
                 __nv_bfloat16* __restrict__ wlo)
{
    const int tid = threadIdx.x;
    if (blockIdx.x == 0) {
        // ---- sort: group samples by expert; emit compacted job list ----
        __shared__ int cnt[E_TASKS];
        __shared__ int off[E_TASKS];
        __shared__ int cur[E_TASKS];
        if (tid < E_TASKS) { cnt[tid] = 0; cur[tid] = 0; }
        __syncthreads();
        for (int n = tid; n < N_SAMPLES; n += 256)
            atomicAdd(&cnt[keys[n]], 1);
        __syncthreads();
        if (tid == 0) {
            int s = 0;
            int j = 0;
            for (int e = 0; e < E_TASKS; e++) {
                off[e] = s; s += cnt[e];
                int tiles = (cnt[e] + BM - 1) / BM;
                for (int m = 0; m < tiles; m++) g_jobs[j++] = (e << 16) | m;
            }
            g_njobs = j;
        }
        __syncthreads();
        if (tid < E_TASKS) { g_counts[tid] = cnt[tid]; g_offsets[tid] = off[tid]; }
        for (int n = tid; n < N_SAMPLES; n += 256) {
            int e = keys[n];
            int p = atomicAdd(&cur[e], 1);
            g_perm[off[e] + p] = n;
        }
    } else if (blockIdx.x <= 256) {
        // ---- split x: 256 blocks x 256 threads x 16 float4 ----
        const int blk = blockIdx.x - 1;
        const size_t base = (size_t)blk * 4096;         // float4 units
        const float4* src = (const float4*)x + base;
        uint2* dh = (uint2*)xhi;
        uint2* dl = (uint2*)xlo;
#pragma unroll
        for (int it = 0; it < 16; it++) {
            int i = tid + it * 256;
            float4 v = src[i];
            uint2 hw, lw;
            split4(v, hw, lw);
            size_t g = base + i;
            dh[g] = hw;
            dl[g] = lw;
        }
    } else {
        // ---- split W1 + L1 partials: 512 blocks ----
        const int blk = blockIdx.x - 257;               // 0..511
        const int C4  = (B_MID * D_IN) / L1_SLICES / 4; // 4096 float4
        const size_t base = (size_t)blk * C4;
        const float4* src = (const float4*)W1 + base;
        uint2* dh = (uint2*)whi;
        uint2* dl = (uint2*)wlo;
        float s = 0.f;
        for (int i = tid; i < C4; i += 256) {
            float4 v = src[i];
            s += fabsf(v.x) + fabsf(v.y) + fabsf(v.z) + fabsf(v.w);
            uint2 hw, lw;
            split4(v, hw, lw);
            size_t g = base + i;
            dh[g] = hw;
            dl[g] = lw;
        }
        __shared__ float red[256];
        red[tid] = s;
        __syncthreads();
        for (int st = 128; st > 0; st >>= 1) {
            if (tid < st) red[tid] += red[tid + st];
            __syncthreads();
        }
        if (tid == 0) g_l1part[blk] = red[0];
    }
}

// ---------------------------------------------------------------------------
// Tensor-core / async-copy helpers (legacy mma.sync path — tcgen05 is not
// available through this bench's compile target)
// ---------------------------------------------------------------------------
__device__ __forceinline__ uint32_t smem_u32(const void* p) {
    return (uint32_t)__cvta_generic_to_shared(p);
}
__device__ __forceinline__ void ldsm_x4(uint32_t& r0, uint32_t& r1,
                                        uint32_t& r2, uint32_t& r3, uint32_t a) {
    asm volatile("ldmatrix.sync.aligned.m8n8.x4.shared.b16 {%0,%1,%2,%3}, [%4];"
                 : "=r"(r0), "=r"(r1), "=r"(r2), "=r"(r3) : "r"(a));
}
__device__ __forceinline__ void mma_bf16(float (&d)[4], const uint32_t (&a)[4],
                                         const uint32_t (&b)[2]) {
    asm volatile("mma.sync.aligned.m16n8k16.row.col.f32.bf16.bf16.f32 "
                 "{%0,%1,%2,%3}, {%4,%5,%6,%7}, {%8,%9}, {%0,%1,%2,%3};"
                 : "+f"(d[0]), "+f"(d[1]), "+f"(d[2]), "+f"(d[3])
                 : "r"(a[0]), "r"(a[1]), "r"(a[2]), "r"(a[3]),
                   "r"(b[0]), "r"(b[1]));
}
__device__ __forceinline__ void cp16(uint32_t dst, const void* src, bool valid) {
    int sz = valid ? 16 : 0;   // sz=0 -> zero-fill
    asm volatile("cp.async.cg.shared.global [%0], [%1], 16, %2;"
                 :: "r"(dst), "l"(src), "r"(sz));
}
__device__ __forceinline__ void cp_commit() {
    asm volatile("cp.async.commit_group;");
}
__device__ __forceinline__ void cp_wait0() {
    asm volatile("cp.async.wait_group 0;");
}

// ---------------------------------------------------------------------------
// Kernel 2: grouped bf16x3 GEMM + fused layer-2 partial, job-list driven.
// h = relu(Xg @ W1[e]^T + b1[e]); p[n][nblk] = h(128 cols) . W2[e] slice
// Block tile 64x128x64, 8 warps (2m x 4n), warp tile 32x32, 2-stage.
// Mainloop/epilogue identical to the measured-best R11/R13/R14/R16 config.
// ---------------------------------------------------------------------------
__global__ __launch_bounds__(NTHREADS, 2)
void gemm1_kernel(const float* __restrict__ b1, const float* __restrict__ W2)
{
    if ((int)blockIdx.y >= g_njobs) return;
    const int job = g_jobs[blockIdx.y];
    const int e   = job >> 16;
    const int m0  = (job & 0xffff) * BM;
    const int cnt = g_counts[e];
    const int off = g_offsets[e];
    const int nblk = blockIdx.x;
    const int n0  = nblk * BN;

    extern __shared__ __align__(16) char smem_dyn[];
    int*   rows  = (int*)(smem_dyn + OFF_ROWS);
    float* spart = (float*)(smem_dyn + OFF_PART);   // [64][4]

    const int tid  = threadIdx.x;
    const int lane = tid & 31;
    const int warp = tid >> 5;
    const int wm   = warp >> 2;  // 0..1
    const int wn   = warp & 3;   // 0..3

    if (tid < BM) {
        int m = m0 + tid;
        rows[tid] = (m < cnt) ? g_perm[off + m] : -1;
    }
    __syncthreads();

    const uint32_t sbase = smem_u32(smem_dyn);

    // ---- per-thread cp.async slots: chunk c of 16B, rows r0+32q ----
    const int c  = tid & 7;
    const int r0 = tid >> 3;                         // 0..31
    const uint32_t cpoff = (uint32_t)((c ^ (r0 & 7)) * 16);   // (r&7)==(r0&7)
    uint32_t dstA[2], dstB[4];
    const __nv_bfloat16 *pAh[2], *pAl[2], *pBh[4], *pBl[4];
    bool vA[2];
#pragma unroll
    for (int q = 0; q < 2; q++) {
        int r = r0 + 32 * q;
        dstA[q] = (uint32_t)r * 128u + cpoff;
        int gr = rows[r];
        vA[q] = gr >= 0;
        pAh[q] = g_xhi + (size_t)(vA[q] ? gr : 0) * D_IN + c * 8;
        pAl[q] = g_xlo + (size_t)(vA[q] ? gr : 0) * D_IN + c * 8;
    }
#pragma unroll
    for (int q = 0; q < 4; q++) {
        int r = r0 + 32 * q;
        dstB[q] = (uint32_t)r * 128u + cpoff;
        size_t wb = (size_t)(e * B_MID + n0 + r) * D_IN + c * 8;
        pBh[q] = g_whi + wb;
        pBl[q] = g_wlo + wb;
    }

    // ---- per-warp fragment addressing constants ----
    uint32_t aRowBase[2], aSw[2];
#pragma unroll
    for (int i = 0; i < 2; i++) {
        int arow = wm * 32 + i * 16 + (lane & 15);
        aRowBase[i] = (uint32_t)arow * 128u;
        aSw[i] = (uint32_t)(arow & 7);
    }
    const uint32_t aD = (uint32_t)(lane >> 4);
    uint32_t bPairBase[2];
#pragma unroll
    for (int p = 0; p < 2; p++) {
        int brow = wn * 32 + p * 16 + ((lane >> 4) & 1) * 8 + (lane & 7);
        bPairBase[p] = (uint32_t)brow * 128u;
    }
    const uint32_t bSw = (uint32_t)(lane & 7);
    const uint32_t bD  = (uint32_t)((lane >> 3) & 1);

    float acc[2][4][4];
#pragma unroll
    for (int i = 0; i < 2; i++)
#pragma unroll
        for (int j = 0; j < 4; j++)
#pragma unroll
            for (int q = 0; q < 4; q++) acc[i][j][q] = 0.f;

#define TISSUE(s, kbase)                                                      \
    do {                                                                      \
        uint32_t sb_ = sbase + (s) * STAGE_B;                                 \
        _Pragma("unroll")                                                     \
        for (int q = 0; q < 2; q++) {                                         \
            cp16(sb_ + dstA[q],         pAh[q] + (kbase), vA[q]);             \
            cp16(sb_ + ST_AL + dstA[q], pAl[q] + (kbase), vA[q]);             \
        }                                                                     \
        _Pragma("unroll")                                                     \
        for (int q = 0; q < 4; q++) {                                         \
            cp16(sb_ + ST_BH + dstB[q], pBh[q] + (kbase), true);              \
            cp16(sb_ + ST_BL + dstB[q], pBl[q] + (kbase), true);              \
        }                                                                     \
    } while (0)

#define COMPUTE_T(t)                                                          \
    do {                                                                      \
        uint32_t bhf[4][2], blf[4][2];                                        \
        _Pragma("unroll")                                                     \
        for (int p = 0; p < 2; p++) {                                         \
            uint32_t o = bPairBase[p] + ((((2u * (t)) | bD) ^ bSw) << 4);     \
            ldsm_x4(bhf[2*p][0], bhf[2*p][1], bhf[2*p+1][0], bhf[2*p+1][1],   \
                    bH + o);                                                  \
            ldsm_x4(blf[2*p][0], blf[2*p][1], blf[2*p+1][0], blf[2*p+1][1],   \
                    bL + o);                                                  \
        }                                                                     \
        _Pragma("unroll")                                                     \
        for (int i = 0; i < 2; i++) {                                         \
            uint32_t o = aRowBase[i] + ((((2u * (t)) | aD) ^ aSw[i]) << 4);   \
            uint32_t ah[4], al[4];                                            \
            ldsm_x4(ah[0], ah[1], ah[2], ah[3], aH + o);                      \
            ldsm_x4(al[0], al[1], al[2], al[3], aL + o);                      \
            _Pragma("unroll")                                                 \
            for (int j = 0; j < 4; j++) {                                     \
                mma_bf16(acc[i][j], ah, bhf[j]);                              \
                mma_bf16(acc[i][j], ah, blf[j]);                              \
                mma_bf16(acc[i][j], al, bhf[j]);                              \
            }                                                                 \
        }                                                                     \
    } while (0)

    TISSUE(0, 0);
    cp_commit();

    for (int it = 0; it < NITER; ++it) {
        const int s = it & 1;
        cp_wait0();          // stage s data landed
        __syncthreads();     // visible to all; prior compute done before issue

        const uint32_t aH = sbase + s * STAGE_B;
        const uint32_t aL = aH + ST_AL;
        const uint32_t bH = aH + ST_BH;
        const uint32_t bL = aH + ST_BL;

        COMPUTE_T(0);
        if (it + 1 < NITER) {          // issue prefetch after t=0: spreads LSU
            TISSUE(1 - s, (it + 1) * BK);
            cp_commit();
        }
        COMPUTE_T(1);
        COMPUTE_T(2);
        COMPUTE_T(3);
    }
#undef TISSUE
#undef COMPUTE_T

    // ---- fused epilogue: h = relu(acc+b1); partial = h . W2-slice ----
    const int g  = lane >> 2;
    const int cq = lane & 3;
    float p[2][2];   // [i][row-half]
#pragma unroll
    for (int i = 0; i < 2; i++) { p[i][0] = 0.f; p[i][1] = 0.f; }

#pragma unroll
    for (int j = 0; j < 4; j++) {
        int gcol = n0 + wn * 32 + j * 8 + 2 * cq;
        float2 bb = *(const float2*)(b1 + e * B_MID + gcol);
        float2 ww = *(const float2*)(W2 + e * B_MID + gcol);
#pragma unroll
        for (int i = 0; i < 2; i++) {
            float h0 = fmaxf(acc[i][j][0] + bb.x, 0.f);
            float h1 = fmaxf(acc[i][j][1] + bb.y, 0.f);
            float h2 = fmaxf(acc[i][j][2] + bb.x, 0.f);
            float h3 = fmaxf(acc[i][j][3] + bb.y, 0.f);
            p[i][0] = fmaf(h0, ww.x, fmaf(h1, ww.y, p[i][0]));
            p[i][1] = fmaf(h2, ww.x, fmaf(h3, ww.y, p[i][1]));
        }
    }
    // reduce across the 4 lanes of each quad (fixed butterfly order)
#pragma unroll
    for (int i = 0; i < 2; i++)
#pragma unroll
        for (int hh = 0; hh < 2; hh++) {
            p[i][hh] += __shfl_xor_sync(0xffffffffu, p[i][hh], 1);
            p[i][hh] += __shfl_xor_sync(0xffffffffu, p[i][hh], 2);
        }
    if (cq == 0) {
#pragma unroll
        for (int i = 0; i < 2; i++) {
            int row0 = wm * 32 + i * 16 + g;
            spart[row0 * 4 + wn]       = p[i][0];
            spart[(row0 + 8) * 4 + wn] = p[i][1];
        }
    }
    __syncthreads();
    if (tid < BM && (m0 + tid) < cnt) {
        int r = rows[tid];
        float v = spart[tid * 4 + 0] + spart[tid * 4 + 1]
                + spart[tid * 4 + 2] + spart[tid * 4 + 3];
        g_part[(size_t)r * 4 + nblk] = v;
    }
}

// ---------------------------------------------------------------------------
// Kernel 3: finalize. Blocks 0..15: out[n] from layer-2 partials.
// Block 16: L1 scalar — small terms (b1, W2, b2) computed here (8 warps x 2
// experts; each lane folds its g_l1part slice into the same fixed butterfly).
// ---------------------------------------------------------------------------
__global__ void final_kernel(const int* __restrict__ keys,
                             const float* __restrict__ b1,
                             const float* __restrict__ W2,
                             const float* __restrict__ b2,
                             float* __restrict__ out, int out_size)
{
    const int tid = threadIdx.x;
    if (blockIdx.x < 16) {
        int n = blockIdx.x * 256 + tid;
        float4 pv = *(const float4*)(g_part + (size_t)n * 4);
        out[n] = pv.x + pv.y + pv.z + pv.w + b2[keys[n]];
    } else if (out_size > N_SAMPLES) {
        __shared__ float l1s[E_TASKS];
        int warp = tid >> 5, lane = tid & 31;
#pragma unroll
        for (int k = 0; k < 2; k++) {
            int e = warp * 2 + k;
            float s = g_l1part[e * L1_SLICES + lane];   // 32 lanes = 32 slices
            for (int i = lane; i < B_MID; i += 32)
                s += fabsf(b1[e * B_MID + i]) + fabsf(W2[e * B_MID + i]);
#pragma unroll
            for (int o = 16; o > 0; o >>= 1)
                s += __shfl_xor_sync(0xffffffffu, s, o);
            if (lane == 0) l1s[e] = s + fabsf(b2[e]);
        }
        __syncthreads();
        if (tid == 0) {
            float tot = 0.f;
            for (int e = 0; e < E_TASKS; e++)
                tot += (float)g_counts[e] * l1s[e];
            out[N_SAMPLES] = L1_LAMBDA * tot;
        }
    }
}

// ---------------------------------------------------------------------------
extern "C" void kernel_launch(void* const* d_in, const int* in_sizes, int n_in,
                              void* d_out, int out_size)
{
    const float* x    = (const float*)d_in[0];
    const int*   keys = (const int*)  d_in[1];
    const float* W1   = (const float*)d_in[2];
    const float* b1   = (const float*)d_in[3];
    const float* W2   = (const float*)d_in[4];
    const float* b2   = (const float*)d_in[5];
    float* out = (float*)d_out;

    cudaFuncSetAttribute(gemm1_kernel,
                         cudaFuncAttributeMaxDynamicSharedMemorySize,
                         SMEM_BYTES);

    __nv_bfloat16 *xhi, *xlo, *whi, *wlo;
    cudaGetSymbolAddress((void**)&xhi, g_xhi);
    cudaGetSymbolAddress((void**)&xlo, g_xlo);
    cudaGetSymbolAddress((void**)&whi, g_whi);
    cudaGetSymbolAddress((void**)&wlo, g_wlo);

    prep_kernel<<<769, 256>>>(x, W1, keys, xhi, xlo, whi, wlo);

    dim3 grid(B_MID / BN, MAXJOBS);   // (4, 80) job-list driven
    gemm1_kernel<<<grid, NTHREADS, SMEM_BYTES>>>(b1, W2);

    final_kernel<<<17, 256>>>(keys, b1, W2, b2, out, out_size);
}